// round 10
// baseline (speedup 1.0000x reference)
#include <cuda_runtime.h>
#include <cuda_fp16.h>
#include <cstdint>

#define TOK 16384
#define CMP 8192
#define HID 2048
#define ITR 8192

#define BM 128
#define BN 128
#define BK 64            // fp16 elements per K-chunk = 128 bytes per row

// fp16 operand scratch + intermediates
__device__ __half g_xg[(size_t)CMP * HID];
__device__ __half g_wg[(size_t)ITR * HID];
__device__ __half g_wu[(size_t)ITR * HID];
__device__ __half g_wd[(size_t)HID * ITR];
__device__ __half g_h [(size_t)CMP * ITR];
__device__ float  g_dc[(size_t)CMP * HID];

// ---------------------------------------------------------------- helpers
static __device__ __forceinline__ float silu_f(float x){ return x / (1.0f + __expf(-x)); }

static __device__ __forceinline__ uint32_t s2u(const void* p){
    uint32_t a;
    asm("{ .reg .u64 t; cvta.to.shared.u64 t, %1; cvt.u32.u64 %0, t; }" : "=r"(a) : "l"(p));
    return a;
}
static __device__ __forceinline__ void cp16(uint32_t dst, const void* src){
    asm volatile("cp.async.cg.shared.global [%0], [%1], 16;" :: "r"(dst), "l"(src));
}
static __device__ __forceinline__ void cp_commit(){
    asm volatile("cp.async.commit_group;" ::: "memory");
}
template<int N>
static __device__ __forceinline__ void cp_wait(){
    asm volatile("cp.async.wait_group %0;" :: "n"(N) : "memory");
}

// 32-bit-word index (f16x2 granularity) of element (row r, k) in a
// [rows][64-half] tile whose 16B chunks are XOR-swizzled: chunk j -> j ^ (r&7).
// k must be even. Conflict-free for cp.async stores and mma fragment loads.
static __device__ __forceinline__ int hidx(int r, int k){
    return r * 32 + ((((k >> 3) ^ r) & 7) << 2) + ((k >> 1) & 3);
}

static __device__ __forceinline__ void mma_f16(float* d, const unsigned* a,
                                               const unsigned* b){
    asm volatile(
        "mma.sync.aligned.m16n8k16.row.col.f32.f16.f16.f32 "
        "{%0,%1,%2,%3}, {%4,%5,%6,%7}, {%8,%9}, {%0,%1,%2,%3};\n"
        : "+f"(d[0]), "+f"(d[1]), "+f"(d[2]), "+f"(d[3])
        : "r"(a[0]), "r"(a[1]), "r"(a[2]), "r"(a[3]), "r"(b[0]), "r"(b[1]));
}

// ---------------------------------------------------------------- GEMM
// C = A[M,K] @ B^T   (A,B fp16 K-major; fp32 accumulate).
// FUSED=1: two B matrices (gate/up); epilogue C = half(silu(g) * u).
// FUSED=0: single B; fp32 store.
// Block tile 128x128. 8 warps as 2(m) x 4(n); warp tile 64x32 per B matrix.
template<int FUSED, int NST>
__global__ void __launch_bounds__(256, FUSED ? 1 : 2)
gemm_mma(const __half* __restrict__ A, const __half* __restrict__ B0,
         const __half* __restrict__ B1, void* __restrict__ Cv, int N, int K)
{
    extern __shared__ char smem[];
    constexpr int SAB = BM * BK * 2;                      // 16384 B
    constexpr int SBB = BN * BK * 2;                      // 16384 B
    constexpr int STG = SAB + SBB * (FUSED ? 2 : 1);      // bytes per stage

    const int tid  = threadIdx.x;
    const int lane = tid & 31;
    const int warp = tid >> 5;
    const int gid  = lane >> 2;          // 0..7
    const int tig  = lane & 3;           // 0..3
    const int wm   = (warp & 1) * 64;    // 2 m-groups
    const int wn   = (warp >> 1) * 32;   // 4 n-groups
    const int m0   = blockIdx.y * BM;
    const int n0   = blockIdx.x * BN;
    const int KT   = K / BK;

    // producer assignment: 8 chunks (16B = 8 halves) per 128B row
    const int lrow = tid >> 3;           // 0..31
    const int lj   = tid & 7;            // chunk 0..7
    const uint32_t sbase = s2u(smem);
    const uint32_t soffs = (uint32_t)(lrow * 128 + ((lj ^ (lrow & 7)) << 4));

    const __half* Ap  = A  + (size_t)(m0 + lrow) * K + lj * 8;
    const __half* B0p = B0 + (size_t)(n0 + lrow) * K + lj * 8;
    const __half* B1p = FUSED ? (B1 + (size_t)(n0 + lrow) * K + lj * 8) : B0;

    auto load_stage = [&](int st, int kt){
        const uint32_t tb = sbase + (uint32_t)st * STG + soffs;
        const size_t go = (size_t)kt * BK;
        #pragma unroll
        for (int i = 0; i < 4; i++)
            cp16(tb + i * 4096, Ap + (size_t)(32 * i) * K + go);
        #pragma unroll
        for (int i = 0; i < 4; i++) {
            cp16(tb + SAB + i * 4096, B0p + (size_t)(32 * i) * K + go);
            if (FUSED)
                cp16(tb + SAB + SBB + i * 4096, B1p + (size_t)(32 * i) * K + go);
        }
        cp_commit();
    };

    float accG[4][4][4];
    float accU[FUSED ? 4 : 1][4][4];
    #pragma unroll
    for (int mi = 0; mi < 4; mi++)
        #pragma unroll
        for (int nf = 0; nf < 4; nf++)
            #pragma unroll
            for (int j = 0; j < 4; j++) {
                accG[mi][nf][j] = 0.0f;
                if (FUSED) accU[mi][nf][j] = 0.0f;
            }

    // prologue: fill NST-1 stages
    #pragma unroll
    for (int s = 0; s < NST - 1; s++) load_stage(s, s);

    for (int kt = 0; kt < KT; kt++) {
        cp_wait<NST - 2>();
        __syncthreads();

        const int nxt = kt + NST - 1;
        if (nxt < KT) load_stage(nxt % NST, nxt);
        else          cp_commit();          // keep group count uniform

        const unsigned* sA = (const unsigned*)(smem + (kt % NST) * STG);
        const unsigned* sG = (const unsigned*)(smem + (kt % NST) * STG + SAB);
        const unsigned* sU = (const unsigned*)(smem + (kt % NST) * STG + SAB + SBB);

        #pragma unroll
        for (int ks = 0; ks < 4; ks++) {
            const int kk = ks * 16 + 2 * tig;     // even k for f16x2 loads

            unsigned af[4][4];
            #pragma unroll
            for (int mi = 0; mi < 4; mi++) {
                const int m = wm + mi * 16 + gid;
                af[mi][0] = sA[hidx(m,     kk)];
                af[mi][1] = sA[hidx(m + 8, kk)];
                af[mi][2] = sA[hidx(m,     kk + 8)];
                af[mi][3] = sA[hidx(m + 8, kk + 8)];
            }
            unsigned bg[4][2], bu[4][2];
            #pragma unroll
            for (int nf = 0; nf < 4; nf++) {
                const int n = wn + nf * 8 + gid;
                bg[nf][0] = sG[hidx(n, kk)];
                bg[nf][1] = sG[hidx(n, kk + 8)];
                if (FUSED) {
                    bu[nf][0] = sU[hidx(n, kk)];
                    bu[nf][1] = sU[hidx(n, kk + 8)];
                }
            }
            #pragma unroll
            for (int mi = 0; mi < 4; mi++)
                #pragma unroll
                for (int nf = 0; nf < 4; nf++) {
                    mma_f16(accG[mi][nf], af[mi], bg[nf]);
                    if (FUSED) mma_f16(accU[mi][nf], af[mi], bu[nf]);
                }
        }
    }

    // ---------------- epilogue
    #pragma unroll
    for (int mi = 0; mi < 4; mi++) {
        #pragma unroll
        for (int nf = 0; nf < 4; nf++) {
            const int row = m0 + wm + mi * 16 + gid;
            const int col = n0 + wn + nf * 8 + tig * 2;
            const size_t i0 = (size_t)row * N + col;
            const size_t i1 = i0 + (size_t)8 * N;
            if (FUSED) {
                __half* C = (__half*)Cv;
                __half2 v0 = __floats2half2_rn(
                    silu_f(accG[mi][nf][0]) * accU[mi][nf][0],
                    silu_f(accG[mi][nf][1]) * accU[mi][nf][1]);
                __half2 v1 = __floats2half2_rn(
                    silu_f(accG[mi][nf][2]) * accU[mi][nf][2],
                    silu_f(accG[mi][nf][3]) * accU[mi][nf][3]);
                *(__half2*)(C + i0) = v0;
                *(__half2*)(C + i1) = v1;
            } else {
                float* C = (float*)Cv;
                float2 v0 = make_float2(accG[mi][nf][0], accG[mi][nf][1]);
                float2 v1 = make_float2(accG[mi][nf][2], accG[mi][nf][3]);
                *(float2*)(C + i0) = v0;
                *(float2*)(C + i1) = v1;
            }
        }
    }
}

// ---------------------------------------------------------------- prep + scatter
__global__ void conv_h(const float* __restrict__ in, __half* __restrict__ out, size_t n){
    size_t i = (size_t)blockIdx.x * blockDim.x + threadIdx.x;
    const size_t stride = (size_t)gridDim.x * blockDim.x;
    for (; i < n / 4; i += stride) {
        float4 v = ((const float4*)in)[i];
        __half2 lo = __floats2half2_rn(v.x, v.y);
        __half2 hi = __floats2half2_rn(v.z, v.w);
        ((__half2*)out)[i * 2]     = lo;
        ((__half2*)out)[i * 2 + 1] = hi;
    }
}

__global__ void gather_conv_h(const float* __restrict__ x, const int* __restrict__ fg,
                              __half* __restrict__ out){
    const int c = blockIdx.x;
    const int src = __ldg(fg + c);
    const float4* s = (const float4*)(x + (size_t)src * HID);
    __half2* d = (__half2*)(out + (size_t)c * HID);
    for (int j = threadIdx.x; j < HID / 4; j += blockDim.x) {
        float4 v = s[j];
        d[j * 2]     = __floats2half2_rn(v.x, v.y);
        d[j * 2 + 1] = __floats2half2_rn(v.z, v.w);
    }
}

__global__ void scatter_rows(const float* __restrict__ dc, const int* __restrict__ sc,
                             float* __restrict__ out){
    const int n = blockIdx.x;
    const int c = __ldg(sc + n);
    const float4* s = (const float4*)(dc + (size_t)c * HID);
    float4* d = (float4*)(out + (size_t)n * HID);
    #pragma unroll
    for (int j = threadIdx.x; j < HID / 4; j += 256)
        d[j] = s[j];
}

// ---------------------------------------------------------------- launch
extern "C" void kernel_launch(void* const* d_in, const int* in_sizes, int n_in,
                              void* d_out, int out_size)
{
    (void)in_sizes; (void)n_in; (void)out_size;
    const float* x  = (const float*)d_in[0];   // [16384, 2048]
    const float* Wg = (const float*)d_in[1];   // [8192, 2048]
    const float* Wu = (const float*)d_in[2];   // [8192, 2048]
    const float* Wd = (const float*)d_in[3];   // [2048, 8192]
    const int*   fg = (const int*)d_in[4];     // [8192]
    const int*   sc = (const int*)d_in[5];     // [16384]
    float* out = (float*)d_out;                // [16384, 2048]

    __half *xg, *wg, *wu, *wd, *h;
    float *dc;
    cudaGetSymbolAddress((void**)&xg, g_xg);
    cudaGetSymbolAddress((void**)&wg, g_wg);
    cudaGetSymbolAddress((void**)&wu, g_wu);
    cudaGetSymbolAddress((void**)&wd, g_wd);
    cudaGetSymbolAddress((void**)&h,  g_h);
    cudaGetSymbolAddress((void**)&dc, g_dc);

    const int SMEM_F = 4 * (BM + 2 * BN) * BK * 2;   // 4 stages * 48KB = 196608
    const int SMEM_P = 3 * (BM + 1 * BN) * BK * 2;   // 3 stages * 32KB =  98304
    cudaFuncSetAttribute((const void*)gemm_mma<1, 4>,
                         cudaFuncAttributeMaxDynamicSharedMemorySize, SMEM_F);
    cudaFuncSetAttribute((const void*)gemm_mma<0, 3>,
                         cudaFuncAttributeMaxDynamicSharedMemorySize, SMEM_P);

    // RN-round operands to fp16 (gather folded into x pass)
    gather_conv_h<<<CMP, 256>>>(x, fg, xg);
    conv_h<<<4096, 256>>>(Wg, wg, (size_t)ITR * HID);
    conv_h<<<4096, 256>>>(Wu, wu, (size_t)ITR * HID);
    conv_h<<<4096, 256>>>(Wd, wd, (size_t)HID * ITR);

    // h = half( silu(xg @ Wg^T) * (xg @ Wu^T) )   [fused dual-accumulator]
    gemm_mma<1, 4><<<dim3(ITR / BN, CMP / BM), 256, SMEM_F>>>(xg, wg, wu, h, ITR, HID);
    // dc = h @ Wd^T
    gemm_mma<0, 3><<<dim3(HID / BN, CMP / BM), 256, SMEM_P>>>(h, wd, nullptr, dc, HID, ITR);
    // out = dc[sc]
    scatter_rows<<<TOK, 256>>>(dc, sc, out);
}